// round 6
// baseline (speedup 1.0000x reference)
#include <cuda_runtime.h>
#include <stdint.h>

// Problem shape is fixed by setup_inputs(): B=64, N=4, H=512, W=512, num=1024.
#define BB 64
#define NPLANES 4
#define HH 512
#define WW 512
#define HWPIX (HH * WW)            // 262144
#define WORDS_PER_B (HWPIX / 32)   // 8192
#define NUM 1024
#define IDX_ELEMS (BB * NUM * 2)   // 131072 index values

// Scratch (no allocations allowed): bitmask of valid pixels, word-level
// exclusive prefix of popcounts, and per-batch totals.
__device__ uint32_t g_bits[BB * WORDS_PER_B];   // 2 MiB
__device__ int      g_csum[BB * WORDS_PER_B];   // 2 MiB
__device__ int      g_cnt[BB];

// ---------------------------------------------------------------------------
// Kernel 1: valid[b,p] = (sum_n masks[b,n,p]) > 0.5, packed 32 pixels/word.
// 1 pixel per thread, 4 coalesced plane loads, ballot to pack.
// ---------------------------------------------------------------------------
__global__ __launch_bounds__(256) void k_mask_bits(const float* __restrict__ m) {
    int gid = blockIdx.x * blockDim.x + threadIdx.x;  // global pixel id in [0, B*HW)
    int b = gid >> 18;            // / HWPIX  (HWPIX = 2^18)
    int p = gid & (HWPIX - 1);
    const float* base = m + (size_t)b * NPLANES * HWPIX + p;
    float s = base[0] + base[HWPIX] + base[2 * HWPIX] + base[3 * HWPIX];
    unsigned bal = __ballot_sync(0xFFFFFFFFu, s > 0.5f);
    if ((threadIdx.x & 31) == 0) g_bits[gid >> 5] = bal;
}

// ---------------------------------------------------------------------------
// Kernel 2: per-batch exclusive prefix over the 8192 word popcounts.
// One block of 256 threads per batch; each thread owns 32 consecutive words.
// ---------------------------------------------------------------------------
__global__ __launch_bounds__(256) void k_scan() {
    __shared__ int sums[256];
    int b = blockIdx.x;
    int t = threadIdx.x;
    const uint32_t* bits = g_bits + (size_t)b * WORDS_PER_B;
    int base = t * 32;
    int local[32];
    int acc = 0;
#pragma unroll
    for (int i = 0; i < 32; i++) {
        local[i] = __popc(bits[base + i]);
        acc += local[i];
    }
    sums[t] = acc;
    __syncthreads();
    // Hillis-Steele inclusive scan over 256 thread sums.
    for (int off = 1; off < 256; off <<= 1) {
        int v = (t >= off) ? sums[t - off] : 0;
        __syncthreads();
        sums[t] += v;
        __syncthreads();
    }
    int excl = sums[t] - acc;   // exclusive prefix for this thread's chunk
    int run = excl;
    int* cs = g_csum + (size_t)b * WORDS_PER_B;
#pragma unroll
    for (int i = 0; i < 32; i++) {
        cs[base + i] = run;     // bits strictly before word (base+i)
        run += local[i];
    }
    if (t == 255) g_cnt[b] = sums[255];
}

// ---------------------------------------------------------------------------
// Kernel 3: one block per batch, 256 threads, 4 sample points per thread.
// Stage the 32KB word-prefix array in shared; binary search for the word
// containing the t-th set bit, then select that bit inside the word.
// Replicates: r = min(int(u * float(cnt)), cnt-1); pos = searchsorted(csum, r+1).
// Output written as FLOAT32 (harness-supported dtypes are {f32,i32,bf16};
// the int64 reference output is stored as f32 — small ints are exact in f32).
// ---------------------------------------------------------------------------
__global__ __launch_bounds__(256) void k_sample(const float* __restrict__ rand_u,
                                                float* __restrict__ out) {
    __shared__ int s_cs[WORDS_PER_B];   // 32 KiB
    int b = blockIdx.x;
    const int* cs = g_csum + (size_t)b * WORDS_PER_B;
    for (int i = threadIdx.x; i < WORDS_PER_B; i += 256)
        s_cs[i] = cs[i];
    __syncthreads();

    int total = g_cnt[b];
    const uint32_t* bits = g_bits + (size_t)b * WORDS_PER_B;

    for (int pt = threadIdx.x; pt < NUM; pt += 256) {
        float u = rand_u[b * NUM + pt];

        int pos;
        if (total == 0) {
            // reference: cnt = max(total,1)=1, r=0, searchsorted over all-zero
            // csum for target 1 -> insertion point HW.
            pos = HWPIX;
        } else {
            int cnt = total;
            int r = (int)(u * (float)cnt);      // fp32 RN mul, trunc — matches jnp
            if (r > cnt - 1) r = cnt - 1;
            int tgt = r + 1;                    // want the tgt-th set bit (1-indexed)
            // last word w with (#bits before w) < tgt
            int lo = 0, hi = WORDS_PER_B;
            while (lo + 1 < hi) {
                int mid = (lo + hi) >> 1;
                if (s_cs[mid] < tgt) lo = mid; else hi = mid;
            }
            uint32_t wrd = bits[lo];
            int k = tgt - s_cs[lo];             // k-th set bit inside word, k>=1
#pragma unroll 1
            for (int j = 1; j < k; j++) wrd &= wrd - 1;  // drop k-1 lowest set bits
            pos = lo * 32 + (__ffs(wrd) - 1);
        }

        float2 hw;
        hw.x = (float)(pos / WW);
        hw.y = (float)(pos & (WW - 1));
        *reinterpret_cast<float2*>(out + ((size_t)b * NUM + pt) * 2) = hw;
    }
}

// ---------------------------------------------------------------------------
// Kernel 4: fill any output elements beyond the indices with 512 (= H = W),
// in case the harness flattens the (H, W) tuple leaves into d_out too.
// No-op when out_size == IDX_ELEMS.
// ---------------------------------------------------------------------------
__global__ void k_tail(float* __restrict__ out, int tail_n) {
    int i = blockIdx.x * blockDim.x + threadIdx.x;
    if (i < tail_n) out[IDX_ELEMS + i] = 512.0f;
}

extern "C" void kernel_launch(void* const* d_in, const int* in_sizes, int n_in,
                              void* d_out, int out_size) {
    // Identify inputs by size, robust to metadata ordering.
    const float* masks  = nullptr;   // [64,4,512,512] f32 -> 67,108,864 elems
    const float* rand_u = nullptr;   // [64,1024] f32      -> 65,536 elems
    for (int i = 0; i < n_in; i++) {
        if (in_sizes[i] == BB * NPLANES * HWPIX) masks = (const float*)d_in[i];
        else if (in_sizes[i] == BB * NUM)        rand_u = (const float*)d_in[i];
    }
    if (!masks)  masks  = (const float*)d_in[0];
    if (!rand_u) rand_u = (const float*)d_in[1];
    float* out = (float*)d_out;      // [64,1024,2] stored as float32

    k_mask_bits<<<(BB * HWPIX) / 256, 256>>>(masks);
    k_scan<<<BB, 256>>>();
    k_sample<<<BB, 256>>>(rand_u, out);

    int tail_n = out_size - IDX_ELEMS;
    if (tail_n > 0) {
        k_tail<<<(tail_n + 255) / 256, 256>>>(out, tail_n);
    }
}

// round 7
// speedup vs baseline: 1.4552x; 1.4552x over previous
#include <cuda_runtime.h>
#include <stdint.h>

// Problem shape is fixed by setup_inputs(): B=64, N=4, H=512, W=512, num=1024.
#define BB 64
#define NPLANES 4
#define HH 512
#define WW 512
#define HWPIX (HH * WW)            // 262144
#define HW4 (HWPIX / 4)            // 65536 float4s per plane
#define WORDS_PER_B (HWPIX / 32)   // 8192
#define NUM 1024
#define IDX_ELEMS (BB * NUM * 2)   // 131072 index values

// Scratch (no allocations allowed): bitmask of valid pixels.
__device__ uint32_t g_bits[BB * WORDS_PER_B];   // 2 MiB

// ---------------------------------------------------------------------------
// Kernel 1: valid[b,p] = (sum_n masks[b,n,p]) > 0.5, packed 32 pixels/word.
// 4 consecutive pixels per thread via float4 loads (4 LDG.128/thread, MLP=4).
// Nibble of validity bits is OR-combined across 8-lane groups with shfl_xor,
// reproducing the pixel-order bit layout (bit i of word w = pixel 32w+i).
// ---------------------------------------------------------------------------
__global__ __launch_bounds__(256) void k_mask_bits(const float4* __restrict__ m4) {
    int gid4 = blockIdx.x * 256 + threadIdx.x;   // float4 index in [0, B*HW/4)
    int b  = gid4 >> 16;                         // (gid4*4) / HWPIX
    int p4 = gid4 & (HW4 - 1);
    const float4* base = m4 + (size_t)b * NPLANES * HW4 + p4;
    float4 a0 = base[0];
    float4 a1 = base[HW4];
    float4 a2 = base[2 * HW4];
    float4 a3 = base[3 * HW4];
    // Keep the exact association order that validated bit-exact in R6.
    float sx = ((a0.x + a1.x) + a2.x) + a3.x;
    float sy = ((a0.y + a1.y) + a2.y) + a3.y;
    float sz = ((a0.z + a1.z) + a2.z) + a3.z;
    float sw = ((a0.w + a1.w) + a2.w) + a3.w;
    unsigned nib = (unsigned)(sx > 0.5f)
                 | ((unsigned)(sy > 0.5f) << 1)
                 | ((unsigned)(sz > 0.5f) << 2)
                 | ((unsigned)(sw > 0.5f) << 3);
    int l = threadIdx.x & 31;
    unsigned v = nib << ((l & 7) * 4);
    v |= __shfl_xor_sync(0xFFFFFFFFu, v, 1);
    v |= __shfl_xor_sync(0xFFFFFFFFu, v, 2);
    v |= __shfl_xor_sync(0xFFFFFFFFu, v, 4);
    if ((l & 7) == 0) g_bits[gid4 >> 3] = v;     // word = (4*gid4)/32
}

// ---------------------------------------------------------------------------
// Kernel 2 (fused scan + sample + tail): one block per batch, 256 threads.
// Phase A: popcount prefix over the 8192 bit-words, csum kept in SHARED only.
// Phase B: 4 sample points per thread; 13-level binary search in shared,
//          then k-th-set-bit select from the L2-resident bit word.
// Replicates: r = min(int(u * float(cnt)), cnt-1); pos = searchsorted(csum, r+1).
// Phase C: block 0 fills the flattened (H, W) tail with 512.0f.
// Output is float32 (small ints exact in f32).
// ---------------------------------------------------------------------------
__global__ __launch_bounds__(256) void k_scan_sample(const float* __restrict__ rand_u,
                                                     float* __restrict__ out,
                                                     int tail_n) {
    __shared__ int s_cs[WORDS_PER_B];   // 32 KiB word-level exclusive prefix
    __shared__ int sums[256];
    __shared__ int s_total;
    int b = blockIdx.x;
    int t = threadIdx.x;

    // --- Phase A: per-thread popcounts of 32 consecutive words (8x uint4) ---
    const uint4* bits4 = reinterpret_cast<const uint4*>(g_bits + (size_t)b * WORDS_PER_B);
    int local[32];
    int acc = 0;
#pragma unroll
    for (int i = 0; i < 8; i++) {
        uint4 w = bits4[t * 8 + i];
        local[i * 4 + 0] = __popc(w.x);
        local[i * 4 + 1] = __popc(w.y);
        local[i * 4 + 2] = __popc(w.z);
        local[i * 4 + 3] = __popc(w.w);
        acc += local[i * 4 + 0] + local[i * 4 + 1] + local[i * 4 + 2] + local[i * 4 + 3];
    }
    sums[t] = acc;
    __syncthreads();
    // Hillis-Steele inclusive scan over 256 thread sums.
    for (int off = 1; off < 256; off <<= 1) {
        int v = (t >= off) ? sums[t - off] : 0;
        __syncthreads();
        sums[t] += v;
        __syncthreads();
    }
    int run = sums[t] - acc;            // exclusive prefix for this thread's chunk
    int base = t * 32;
#pragma unroll
    for (int i = 0; i < 32; i++) {
        s_cs[base + i] = run;           // bits strictly before word (base+i)
        run += local[i];
    }
    if (t == 255) s_total = sums[255];
    __syncthreads();

    // --- Phase B: sample 1024 points (4 per thread) ---
    int total = s_total;
    const uint32_t* bits = g_bits + (size_t)b * WORDS_PER_B;

    for (int pt = t; pt < NUM; pt += 256) {
        float u = rand_u[b * NUM + pt];

        int pos;
        if (total == 0) {
            // reference: cnt = max(total,1) = 1, r = 0, searchsorted over
            // all-zero csum for target 1 -> insertion point HW.
            pos = HWPIX;
        } else {
            int cnt = total;
            int r = (int)(u * (float)cnt);      // fp32 RN mul, trunc — matches jnp
            if (r > cnt - 1) r = cnt - 1;
            int tgt = r + 1;                    // want the tgt-th set bit (1-indexed)
            // last word w with (#bits before w) < tgt
            int lo = 0, hi = WORDS_PER_B;
            while (lo + 1 < hi) {
                int mid = (lo + hi) >> 1;
                if (s_cs[mid] < tgt) lo = mid; else hi = mid;
            }
            uint32_t wrd = bits[lo];
            int k = tgt - s_cs[lo];             // k-th set bit inside word, k>=1
#pragma unroll 1
            for (int j = 1; j < k; j++) wrd &= wrd - 1;  // drop k-1 lowest set bits
            pos = lo * 32 + (__ffs(wrd) - 1);
        }

        float2 hw;
        hw.x = (float)(pos / WW);
        hw.y = (float)(pos & (WW - 1));
        *reinterpret_cast<float2*>(out + ((size_t)b * NUM + pt) * 2) = hw;
    }

    // --- Phase C: tail fill ((H, W) tuple leaves flattened into d_out) ---
    if (b == 0) {
        for (int i = t; i < tail_n; i += 256) out[IDX_ELEMS + i] = 512.0f;
    }
}

extern "C" void kernel_launch(void* const* d_in, const int* in_sizes, int n_in,
                              void* d_out, int out_size) {
    // Identify inputs by size, robust to metadata ordering.
    const float* masks  = nullptr;   // [64,4,512,512] f32 -> 67,108,864 elems
    const float* rand_u = nullptr;   // [64,1024] f32      -> 65,536 elems
    for (int i = 0; i < n_in; i++) {
        if (in_sizes[i] == BB * NPLANES * HWPIX) masks = (const float*)d_in[i];
        else if (in_sizes[i] == BB * NUM)        rand_u = (const float*)d_in[i];
    }
    if (!masks)  masks  = (const float*)d_in[0];
    if (!rand_u) rand_u = (const float*)d_in[1];
    float* out = (float*)d_out;      // [64,1024,2] stored as float32 (+ tail)

    int tail_n = out_size - IDX_ELEMS;
    if (tail_n < 0) tail_n = 0;

    k_mask_bits<<<(BB * HW4) / 256, 256>>>(reinterpret_cast<const float4*>(masks));
    k_scan_sample<<<BB, 256>>>(rand_u, out, tail_n);
}

// round 8
// speedup vs baseline: 1.5787x; 1.0849x over previous
#include <cuda_runtime.h>
#include <stdint.h>

// Problem shape is fixed by setup_inputs(): B=64, N=4, H=512, W=512, num=1024.
#define BB 64
#define NPLANES 4
#define HH 512
#define WW 512
#define HWPIX (HH * WW)            // 262144
#define HW4 (HWPIX / 4)            // 65536 float4s per plane
#define WORDS_PER_B (HWPIX / 32)   // 8192
#define NUM 1024
#define IDX_ELEMS (BB * NUM * 2)   // 131072 index values
#define PARTS 4                    // sample blocks per batch

// Scratch (no allocations allowed): bitmask of valid pixels.
__device__ uint32_t g_bits[BB * WORDS_PER_B];   // 2 MiB

// ---------------------------------------------------------------------------
// Kernel 1: valid[b,p] = (sum_n masks[b,n,p]) > 0.5, packed 32 pixels/word.
// 4 consecutive pixels per thread via float4 loads (4 LDG.128/thread, MLP=4).
// Measured at ~6.7 TB/s effective — at the LTS/DRAM cap; leave unchanged.
// ---------------------------------------------------------------------------
__global__ __launch_bounds__(256) void k_mask_bits(const float4* __restrict__ m4) {
    int gid4 = blockIdx.x * 256 + threadIdx.x;   // float4 index in [0, B*HW/4)
    int b  = gid4 >> 16;                         // (gid4*4) / HWPIX
    int p4 = gid4 & (HW4 - 1);
    const float4* base = m4 + (size_t)b * NPLANES * HW4 + p4;
    float4 a0 = base[0];
    float4 a1 = base[HW4];
    float4 a2 = base[2 * HW4];
    float4 a3 = base[3 * HW4];
    // Keep the exact association order that validated bit-exact.
    float sx = ((a0.x + a1.x) + a2.x) + a3.x;
    float sy = ((a0.y + a1.y) + a2.y) + a3.y;
    float sz = ((a0.z + a1.z) + a2.z) + a3.z;
    float sw = ((a0.w + a1.w) + a2.w) + a3.w;
    unsigned nib = (unsigned)(sx > 0.5f)
                 | ((unsigned)(sy > 0.5f) << 1)
                 | ((unsigned)(sz > 0.5f) << 2)
                 | ((unsigned)(sw > 0.5f) << 3);
    int l = threadIdx.x & 31;
    unsigned v = nib << ((l & 7) * 4);
    v |= __shfl_xor_sync(0xFFFFFFFFu, v, 1);
    v |= __shfl_xor_sync(0xFFFFFFFFu, v, 2);
    v |= __shfl_xor_sync(0xFFFFFFFFu, v, 4);
    if ((l & 7) == 0) g_bits[gid4 >> 3] = v;     // word = (4*gid4)/32
}

// ---------------------------------------------------------------------------
// Kernel 2 (fused scan + sample + tail): PARTS blocks per batch, 256 threads.
// Each block redundantly builds the per-batch word prefix in shared (bits are
// L2-resident: 2 MiB total, freshly written), then handles NUM/PARTS points,
// ONE per thread — quarters the dependent-LDS chain per thread and 4x's the
// resident warps vs the previous 64-block version (occ was 12.6%).
// Replicates: r = min(int(u * float(cnt)), cnt-1); pos = searchsorted(csum, r+1).
// ---------------------------------------------------------------------------
__global__ __launch_bounds__(256) void k_scan_sample(const float* __restrict__ rand_u,
                                                     float* __restrict__ out,
                                                     int tail_n) {
    __shared__ int s_cs[WORDS_PER_B];   // 32 KiB word-level exclusive prefix
    __shared__ int sums[256];
    __shared__ int s_total;
    int b    = blockIdx.x >> 2;         // batch
    int part = blockIdx.x & (PARTS - 1);
    int t = threadIdx.x;

    // --- Phase A: per-thread popcounts of 32 consecutive words (8x uint4) ---
    const uint4* bits4 = reinterpret_cast<const uint4*>(g_bits + (size_t)b * WORDS_PER_B);
    int local[32];
    int acc = 0;
#pragma unroll
    for (int i = 0; i < 8; i++) {
        uint4 w = bits4[t * 8 + i];
        local[i * 4 + 0] = __popc(w.x);
        local[i * 4 + 1] = __popc(w.y);
        local[i * 4 + 2] = __popc(w.z);
        local[i * 4 + 3] = __popc(w.w);
        acc += local[i * 4 + 0] + local[i * 4 + 1] + local[i * 4 + 2] + local[i * 4 + 3];
    }
    sums[t] = acc;
    __syncthreads();
    // Hillis-Steele inclusive scan over 256 thread sums.
    for (int off = 1; off < 256; off <<= 1) {
        int v = (t >= off) ? sums[t - off] : 0;
        __syncthreads();
        sums[t] += v;
        __syncthreads();
    }
    int run = sums[t] - acc;            // exclusive prefix for this thread's chunk
    int base = t * 32;
#pragma unroll
    for (int i = 0; i < 32; i++) {
        s_cs[base + i] = run;           // bits strictly before word (base+i)
        run += local[i];
    }
    if (t == 255) s_total = sums[255];
    __syncthreads();

    // --- Phase B: ONE sample point per thread ---
    int total = s_total;
    const uint32_t* bits = g_bits + (size_t)b * WORDS_PER_B;
    int pt = part * 256 + t;            // this block's slice of the 1024 points
    float u = rand_u[b * NUM + pt];

    int pos;
    if (total == 0) {
        // reference: cnt = max(total,1) = 1, r = 0, searchsorted over
        // all-zero csum for target 1 -> insertion point HW.
        pos = HWPIX;
    } else {
        int cnt = total;
        int r = (int)(u * (float)cnt);      // fp32 RN mul, trunc — matches jnp
        if (r > cnt - 1) r = cnt - 1;
        int tgt = r + 1;                    // want the tgt-th set bit (1-indexed)
        // last word w with (#bits before w) < tgt
        int lo = 0, hi = WORDS_PER_B;
        while (lo + 1 < hi) {
            int mid = (lo + hi) >> 1;
            if (s_cs[mid] < tgt) lo = mid; else hi = mid;
        }
        uint32_t wrd = bits[lo];
        int k = tgt - s_cs[lo];             // k-th set bit inside word, k>=1
        // Fixed-depth 5-step binary select of the k-th set bit (1-indexed).
        int idx = 0;
        int c = __popc(wrd & 0xFFFFu);
        if (k > c) { k -= c; idx += 16; wrd >>= 16; }
        c = __popc(wrd & 0xFFu);
        if (k > c) { k -= c; idx += 8; wrd >>= 8; }
        c = __popc(wrd & 0xFu);
        if (k > c) { k -= c; idx += 4; wrd >>= 4; }
        c = __popc(wrd & 0x3u);
        if (k > c) { k -= c; idx += 2; wrd >>= 2; }
        c = wrd & 1u;
        if (k > c) { idx += 1; }
        pos = lo * 32 + idx;
    }

    float2 hw;
    hw.x = (float)(pos / WW);
    hw.y = (float)(pos & (WW - 1));
    *reinterpret_cast<float2*>(out + ((size_t)b * NUM + pt) * 2) = hw;

    // --- Phase C: tail fill ((H, W) tuple leaves flattened into d_out) ---
    if (blockIdx.x == 0) {
        for (int i = t; i < tail_n; i += 256) out[IDX_ELEMS + i] = 512.0f;
    }
}

extern "C" void kernel_launch(void* const* d_in, const int* in_sizes, int n_in,
                              void* d_out, int out_size) {
    // Identify inputs by size, robust to metadata ordering.
    const float* masks  = nullptr;   // [64,4,512,512] f32 -> 67,108,864 elems
    const float* rand_u = nullptr;   // [64,1024] f32      -> 65,536 elems
    for (int i = 0; i < n_in; i++) {
        if (in_sizes[i] == BB * NPLANES * HWPIX) masks = (const float*)d_in[i];
        else if (in_sizes[i] == BB * NUM)        rand_u = (const float*)d_in[i];
    }
    if (!masks)  masks  = (const float*)d_in[0];
    if (!rand_u) rand_u = (const float*)d_in[1];
    float* out = (float*)d_out;      // [64,1024,2] stored as float32 (+ tail)

    int tail_n = out_size - IDX_ELEMS;
    if (tail_n < 0) tail_n = 0;

    k_mask_bits<<<(BB * HW4) / 256, 256>>>(reinterpret_cast<const float4*>(masks));
    k_scan_sample<<<BB * PARTS, 256>>>(rand_u, out, tail_n);
}